// round 4
// baseline (speedup 1.0000x reference)
#include <cuda_runtime.h>
#include <cuda_fp16.h>
#include <math.h>

#define N_NODES 200000
#define N_EDGES 12800000
#define ALPHA   0.1f
#define DT      0.01f
#define EPS_    1e-9f
#define DIFF_   10.0f
#define HARD    1.57079632679489662f

#define UV_BLOCKS   ((N_NODES + 255) / 256)            // 782
#define N_QUADS     (N_EDGES / 4)                      // 3.2M (N_EDGES % 4 == 0)
#define SCAN_BLOCKS ((N_QUADS + 255) / 256)            // 12500

// Scratch (device globals — no allocation allowed)
__device__ __half2 g_uv[N_NODES];       // pre-rotated (u,v) = e^{-i phi}(x+iy)
__device__ int     g_row[N_NODES + 1];  // CSR row starts (lower_bound of sorted edge_src)
__device__ float2  g_sum[N_NODES];      // per-node gathered sum (pre-rotation)

// ---------------------------------------------------------------------------
// K1 (fused): blocks [0, UV_BLOCKS) compute uv; blocks [UV_BLOCKS, ...) do a
// linear rowscan over sorted edge_src: int4 stream, scatter row starts at
// value boundaries. Both halves are independent.
// ---------------------------------------------------------------------------
__device__ __forceinline__ void fill_rows(int a, int b, int idx)
{
    // lower_bound(k) = idx for all k in (a, b]
    for (int k = a + 1; k <= b; k++) g_row[k] = idx;
}

__global__ void __launch_bounds__(256) prep_kernel(
    const float* __restrict__ phase,
    const float* __restrict__ xy,
    const int*   __restrict__ src)
{
    int b = blockIdx.x;
    if (b < UV_BLOCKS) {
        int i = b * 256 + threadIdx.x;
        if (i >= N_NODES) return;
        float s, c;
        __sincosf(phase[i], &s, &c);
        float2 p = ((const float2*)xy)[i];
        g_uv[i] = __floats2half2_rn(fmaf(c, p.x, s * p.y), fmaf(c, p.y, -s * p.x));
        return;
    }

    int q = (b - UV_BLOCKS) * 256 + threadIdx.x;   // quad index
    if (q >= N_QUADS) return;
    int j = 4 * q;
    int4 s = __ldg((const int4*)(src) + q);
    int s4 = (j + 4 < N_EDGES) ? __ldg(&src[j + 4]) : N_NODES;  // sentinel

    fill_rows(s.x, s.y, j + 1);
    fill_rows(s.y, s.z, j + 2);
    fill_rows(s.z, s.w, j + 3);
    fill_rows(s.w, s4,  j + 4);   // tail thread also writes g_row[N_NODES] = N_EDGES

    if (q == 0) {
        for (int k = 0; k <= s.x; k++) g_row[k] = 0;
    }
}

// ---------------------------------------------------------------------------
// K2: one warp per node. Pure gather + shfl reduce. dst stream evict-first.
// ---------------------------------------------------------------------------
__global__ void __launch_bounds__(256) edge_kernel(
    const int* __restrict__ dst)
{
    int gtid = blockIdx.x * blockDim.x + threadIdx.x;
    int node = gtid >> 5;
    if (node >= N_NODES) return;
    int lane = gtid & 31;

    int beg = g_row[node];
    int end = g_row[node + 1];

    float U = 0.0f, V = 0.0f;
    int j = beg + lane;
    for (; j + 32 < end; j += 64) {
        int d0 = __ldcs(&dst[j]);
        int d1 = __ldcs(&dst[j + 32]);
        float2 f0 = __half22float2(__ldg(&g_uv[d0]));
        float2 f1 = __half22float2(__ldg(&g_uv[d1]));
        U += f0.x + f1.x;
        V += f0.y + f1.y;
    }
    for (; j < end; j += 32) {
        int d = __ldcs(&dst[j]);
        float2 f = __half22float2(__ldg(&g_uv[d]));
        U += f.x;
        V += f.y;
    }

    #pragma unroll
    for (int o = 16; o > 0; o >>= 1) {
        U += __shfl_down_sync(0xffffffffu, U, o);
        V += __shfl_down_sync(0xffffffffu, V, o);
    }
    if (lane == 0) g_sum[node] = make_float2(U, V);
}

// ---------------------------------------------------------------------------
// K3: thread-per-node finalize. Fully coalesced, vectorized.
// ---------------------------------------------------------------------------
__global__ void __launch_bounds__(256) finalize_kernel(
    const float* __restrict__ phase,
    const float* __restrict__ xy,
    const float* __restrict__ xy_dot_old,
    const float* __restrict__ w,
    const float* __restrict__ amp,
    const float* __restrict__ ha,
    float*       __restrict__ out)
{
    int i = blockIdx.x * blockDim.x + threadIdx.x;
    if (i >= N_NODES) return;

    float2 sv = g_sum[i];
    float s, c;
    __sincosf(phase[i], &s, &c);
    float sum_x = fmaf(c, sv.x, -s * sv.y);
    float sum_y = fmaf(s, sv.x,  c * sv.y);

    float2 p  = ((const float2*)xy)[i];
    float2 pd = ((const float2*)xy_dot_old)[i];

    float r2   = fmaf(p.x, p.x, p.y * p.y);
    float a    = ALPHA * (1.0f - r2 * r2);
    float zeta = 1.0f - ha[i] * ((pd.x + EPS_) / (fabsf(pd.x) + EPS_));
    float b    = w[i] / (zeta + EPS_);

    float kx = fmaf(a, p.x, -b * p.y);
    float ky = fmaf(b, p.x,  a * p.y);

    float x_dot = fminf(fmaxf(kx + sum_x, pd.x - DIFF_), pd.x + DIFF_);
    float y_dot = fminf(fmaxf(ky + sum_y, pd.y - DIFF_), pd.y + DIFF_);

    float xn = fmaf(x_dot, DT, p.x);
    float yn = fmaf(y_dot, DT, p.y);
    float ang = fminf(fmaxf(amp[i] * yn, -HARD), HARD);

    out[i] = ang;                                              // angles
    ((float2*)(out + N_NODES))[i]     = make_float2(xn, yn);   // xy_new
    ((float2*)(out + 3 * N_NODES))[i] = p;                     // xy_dot_old_new = xy
}

extern "C" void kernel_launch(void* const* d_in, const int* in_sizes, int n_in,
                              void* d_out, int out_size)
{
    const float* xy         = (const float*)d_in[0];
    const float* xy_dot_old = (const float*)d_in[1];
    const float* phase      = (const float*)d_in[2];
    const float* w          = (const float*)d_in[3];
    const float* amplitudes = (const float*)d_in[4];
    const float* ha         = (const float*)d_in[5];
    const int*   edge_src   = (const int*)d_in[6];
    const int*   edge_dst   = (const int*)d_in[7];
    float* out = (float*)d_out;

    prep_kernel<<<UV_BLOCKS + SCAN_BLOCKS, 256>>>(phase, xy, edge_src);

    int nb_edge = (N_NODES * 32 + 255) / 256;
    edge_kernel<<<nb_edge, 256>>>(edge_dst);

    int nb_nodes = (N_NODES + 255) / 256;
    finalize_kernel<<<nb_nodes, 256>>>(phase, xy, xy_dot_old, w, amplitudes,
                                       ha, out);
}

// round 5
// speedup vs baseline: 1.3324x; 1.3324x over previous
#include <cuda_runtime.h>
#include <cuda_fp16.h>
#include <math.h>

#define N_NODES 200000
#define N_EDGES 12800000
#define ALPHA   0.1f
#define DT      0.01f
#define EPS_    1e-9f
#define DIFF_   10.0f
#define HARD    1.57079632679489662f

#define EPT        16                      // edges per thread (N_EDGES % 16 == 0)
#define N_THREADS  (N_EDGES / EPT)         // 800,000

// Scratch (device globals — no allocation allowed)
__device__ __half2 g_uv[N_NODES];   // pre-rotated (u,v) = e^{-i phi}(x+iy)
__device__ float2  g_sum[N_NODES];  // per-node gathered sum, atomic-accumulated

// ---------------------------------------------------------------------------
// K1: per-node prep. uv[i] = e^{-i phi_i}(x_i + i y_i) as half2; zero g_sum.
// ---------------------------------------------------------------------------
__global__ void __launch_bounds__(256) uv_kernel(
    const float* __restrict__ phase,
    const float* __restrict__ xy)
{
    int i = blockIdx.x * blockDim.x + threadIdx.x;
    if (i >= N_NODES) return;

    float s, c;
    __sincosf(phase[i], &s, &c);
    float2 p = ((const float2*)xy)[i];
    g_uv[i]  = __floats2half2_rn(fmaf(c, p.x, s * p.y), fmaf(c, p.y, -s * p.x));
    g_sum[i] = make_float2(0.0f, 0.0f);
}

// ---------------------------------------------------------------------------
// K2: single fused edge pass. Each thread owns 16 consecutive edges:
//   - 4x int4 coalesced loads of src keys and dst indices (evict-first)
//   - 16 independent uv gathers launched back-to-back (deep MLP)
//   - register run-length scan over the sorted keys, atomicAdd per run
// No CSR, no second pass over edge_src, no shfl scan.
// ---------------------------------------------------------------------------
__global__ void __launch_bounds__(256) edge_kernel(
    const int* __restrict__ src,
    const int* __restrict__ dst)
{
    int t = blockIdx.x * blockDim.x + threadIdx.x;
    if (t >= N_THREADS) return;
    int base = t * EPT;

    // Load 16 keys + 16 dst indices (coalesced int4, streaming)
    int4 s0 = __ldcs((const int4*)(src + base) + 0);
    int4 s1 = __ldcs((const int4*)(src + base) + 1);
    int4 s2 = __ldcs((const int4*)(src + base) + 2);
    int4 s3 = __ldcs((const int4*)(src + base) + 3);
    int4 d0 = __ldcs((const int4*)(dst + base) + 0);
    int4 d1 = __ldcs((const int4*)(dst + base) + 1);
    int4 d2 = __ldcs((const int4*)(dst + base) + 2);
    int4 d3 = __ldcs((const int4*)(dst + base) + 3);

    int k[EPT] = { s0.x, s0.y, s0.z, s0.w,  s1.x, s1.y, s1.z, s1.w,
                   s2.x, s2.y, s2.z, s2.w,  s3.x, s3.y, s3.z, s3.w };
    int di[EPT] = { d0.x, d0.y, d0.z, d0.w,  d1.x, d1.y, d1.z, d1.w,
                    d2.x, d2.y, d2.z, d2.w,  d3.x, d3.y, d3.z, d3.w };

    // Launch all gathers (independent -> 16-deep MLP)
    __half2 h[EPT];
    #pragma unroll
    for (int e = 0; e < EPT; e++) h[e] = __ldg(&g_uv[di[e]]);

    // Run-length scan over sorted keys
    int   cur = k[0];
    float2 f0 = __half22float2(h[0]);
    float U = f0.x, V = f0.y;
    #pragma unroll
    for (int e = 1; e < EPT; e++) {
        float2 f = __half22float2(h[e]);
        if (k[e] != cur) {
            atomicAdd(&g_sum[cur].x, U);
            atomicAdd(&g_sum[cur].y, V);
            cur = k[e];
            U = f.x; V = f.y;
        } else {
            U += f.x; V += f.y;
        }
    }
    atomicAdd(&g_sum[cur].x, U);
    atomicAdd(&g_sum[cur].y, V);
}

// ---------------------------------------------------------------------------
// K3: thread-per-node finalize. Fully coalesced, vectorized.
// ---------------------------------------------------------------------------
__global__ void __launch_bounds__(256) finalize_kernel(
    const float* __restrict__ phase,
    const float* __restrict__ xy,
    const float* __restrict__ xy_dot_old,
    const float* __restrict__ w,
    const float* __restrict__ amp,
    const float* __restrict__ ha,
    float*       __restrict__ out)
{
    int i = blockIdx.x * blockDim.x + threadIdx.x;
    if (i >= N_NODES) return;

    float2 sv = g_sum[i];
    float s, c;
    __sincosf(phase[i], &s, &c);
    float sum_x = fmaf(c, sv.x, -s * sv.y);
    float sum_y = fmaf(s, sv.x,  c * sv.y);

    float2 p  = ((const float2*)xy)[i];
    float2 pd = ((const float2*)xy_dot_old)[i];

    float r2   = fmaf(p.x, p.x, p.y * p.y);
    float a    = ALPHA * (1.0f - r2 * r2);
    float zeta = 1.0f - ha[i] * ((pd.x + EPS_) / (fabsf(pd.x) + EPS_));
    float b    = w[i] / (zeta + EPS_);

    float kx = fmaf(a, p.x, -b * p.y);
    float ky = fmaf(b, p.x,  a * p.y);

    float x_dot = fminf(fmaxf(kx + sum_x, pd.x - DIFF_), pd.x + DIFF_);
    float y_dot = fminf(fmaxf(ky + sum_y, pd.y - DIFF_), pd.y + DIFF_);

    float xn = fmaf(x_dot, DT, p.x);
    float yn = fmaf(y_dot, DT, p.y);
    float ang = fminf(fmaxf(amp[i] * yn, -HARD), HARD);

    out[i] = ang;                                              // angles
    ((float2*)(out + N_NODES))[i]     = make_float2(xn, yn);   // xy_new
    ((float2*)(out + 3 * N_NODES))[i] = p;                     // xy_dot_old_new = xy
}

extern "C" void kernel_launch(void* const* d_in, const int* in_sizes, int n_in,
                              void* d_out, int out_size)
{
    const float* xy         = (const float*)d_in[0];
    const float* xy_dot_old = (const float*)d_in[1];
    const float* phase      = (const float*)d_in[2];
    const float* w          = (const float*)d_in[3];
    const float* amplitudes = (const float*)d_in[4];
    const float* ha         = (const float*)d_in[5];
    const int*   edge_src   = (const int*)d_in[6];
    const int*   edge_dst   = (const int*)d_in[7];
    float* out = (float*)d_out;

    int nb_nodes = (N_NODES + 255) / 256;
    uv_kernel<<<nb_nodes, 256>>>(phase, xy);

    int nb_edge = (N_THREADS + 255) / 256;
    edge_kernel<<<nb_edge, 256>>>(edge_src, edge_dst);

    finalize_kernel<<<nb_nodes, 256>>>(phase, xy, xy_dot_old, w, amplitudes,
                                       ha, out);
}